// round 9
// baseline (speedup 1.0000x reference)
#include <cuda_runtime.h>
#include <stdint.h>

// X (B=4, L=8192, D=32, N=32) fp32, cumsum along L (axis=1).
// Inner = D*N = 1024 contiguous floats per (b,l).
#define BB      4
#define LL      8192
#define INNER   1024
#define SEGW    256                    // lanes per CTA (segment width)
#define NSEG    (INNER / SEGW)         // 4 segments
#define CHUNK   32                     // L rows per tile
#define NT      (LL / CHUNK)           // 256 L-tiles per chain
#define NCHAIN  (BB * NSEG)            // 16 independent (b,seg) chains
#define NTILES  (NCHAIN * NT)          // 4096 tiles per launch
#define GRID    592                    // persistent CTAs (4/SM x 148 SMs)
#define TPL     (NTILES + GRID)        // tickets consumed per launch (exact)

// Lookback state, split:
//   g_flag[tile]        : u32. < fbase stale; == fbase agg ready; == fbase+1 incl ready
//   g_vagg[tile][lane]  : aggregate values (written once per launch per tile)
//   g_vinc[tile][lane]  : inclusive values (written once per launch per tile)
// fbase = 2*epoch + 2, epoch = first_ticket / TPL (monotonic; no reset needed).
__device__ float        g_vagg[(size_t)NTILES * SEGW];   // 4 MiB
__device__ float        g_vinc[(size_t)NTILES * SEGW];   // 4 MiB
__device__ unsigned int g_flag[NTILES];                  // 16 KiB (L2-hot)
__device__ unsigned int g_ticket = 0;                    // monotonic forever

__device__ __forceinline__ unsigned int ld_acq_u32(const unsigned int* p) {
    unsigned int v;
    asm volatile("ld.acquire.gpu.global.b32 %0, [%1];" : "=r"(v) : "l"(p));
    return v;
}
__device__ __forceinline__ void st_rel_u32(unsigned int* p, unsigned int v) {
    asm volatile("st.release.gpu.global.b32 [%0], %1;" :: "l"(p), "r"(v));
}
__device__ __forceinline__ float ld_rel_f32(const float* p) {
    float v;
    asm volatile("ld.relaxed.gpu.global.f32 %0, [%1];" : "=f"(v) : "l"(p));
    return v;
}
__device__ __forceinline__ void cp_async16(uint32_t smem_addr, const void* gmem) {
    asm volatile("cp.async.cg.shared.global [%0], [%1], 16;"
                 :: "r"(smem_addr), "l"(gmem));
}
__device__ __forceinline__ void cp_async_commit() {
    asm volatile("cp.async.commit_group;");
}
__device__ __forceinline__ void cp_async_wait0() {
    asm volatile("cp.async.wait_group 0;");
}

// Element index of row 0, lane 0 of a tile.
__device__ __forceinline__ size_t tile_row0(int tloc) {
    const int chain = tloc & (NCHAIN - 1);
    const int ltile = tloc >> 4;               // NCHAIN = 16
    const int b     = chain >> 2;              // NSEG = 4
    const int seg   = chain & 3;
    return ((size_t)b * LL + (size_t)ltile * CHUNK) * INNER + (size_t)seg * SEGW;
}

__global__ __launch_bounds__(SEGW, 4)
void scan_kernel(const float* __restrict__ X, float* __restrict__ Y) {
    __shared__ float s_buf[CHUNK * SEGW];      // 32 KB staging
    __shared__ unsigned int s_t;
    __shared__ int s_m;

    const int tid  = (int)threadIdx.x;
    const int lane = tid;

    uint32_t s_base;
    asm("{ .reg .u64 t; cvta.to.shared.u64 t, %1; cvt.u32.u64 %0, t; }"
        : "=r"(s_base) : "l"(s_buf));

    if (tid == 0) s_t = atomicAdd(&g_ticket, 1u);
    __syncthreads();

    const unsigned int t0    = s_t;
    const unsigned int epoch = t0 / TPL;                 // launch-unique
    const unsigned int lb    = epoch * TPL;              // launch ticket base
    const unsigned int fbase = epoch * 2u + 2u;          // agg flag; incl = +1
    int tloc = (int)(t0 - lb);
    if (tloc >= NTILES) return;                          // terminating ticket

    // cp.async sweep geometry: 8 sweeps of 4 KB; thread covers 16 B per sweep.
    const int sub  = tid >> 6;
    const int colb = (tid & 63) * 16;
    const uint32_t s_dst0 = s_base + (uint32_t)(sub * 1024 + colb);

    // Prologue prefetch.
    {
        const char* src = (const char*)(X + tile_row0(tloc));
#pragma unroll
        for (int s = 0; s < CHUNK / 4; ++s)
            cp_async16(s_dst0 + (uint32_t)s * 4096u,
                       src + (size_t)(s * 4 + sub) * (INNER * 4) + colb);
        cp_async_commit();
    }

    for (;;) {
        cp_async_wait0();
        __syncthreads();                       // staged tile visible

        float v[CHUNK];
#pragma unroll
        for (int i = 0; i < CHUNK; ++i) v[i] = s_buf[i * SEGW + lane];
#pragma unroll
        for (int i = 1; i < CHUNK; ++i) v[i] += v[i - 1];
        const float total = v[CHUNK - 1];

        const int chain = tloc & (NCHAIN - 1);
        const int ltile = tloc >> 4;
        const int fidx  = chain * NT + ltile;
        const size_t vidx = (size_t)fidx * SEGW + lane;

        // ---- publish aggregate (tile 0 goes straight to inclusive) ----
        if (ltile != 0) g_vagg[vidx] = total;
        else            g_vinc[vidx] = total;
        __threadfence();                       // values visible gpu-wide
        __syncthreads();                       // (also: s_buf reads drained)
        if (tid == 0) {
            st_rel_u32(&g_flag[fidx], ltile == 0 ? fbase + 1u : fbase);
            s_t = atomicAdd(&g_ticket, 1u);
        }
        __syncthreads();
        const int tloc1 = (int)(s_t - lb);

        // Prefetch next tile (overlaps the lookback below).
        if (tloc1 < NTILES) {
            const char* src = (const char*)(X + tile_row0(tloc1));
#pragma unroll
            for (int s = 0; s < CHUNK / 4; ++s)
                cp_async16(s_dst0 + (uint32_t)s * 4096u,
                           src + (size_t)(s * 4 + sub) * (INNER * 4) + colb);
            cp_async_commit();
        }

        // ---- lookback ----
        float excl = 0.0f;
        if (ltile != 0) {
            // Phase F: warp 0 scans 32 flags in parallel per round; finds the
            // latest inclusive tile m with an all-ready suffix up to ltile-1.
            if (tid < 32) {
                int base = ltile - 1;
                int m = 0;
                for (;;) {
                    const int idx = base - tid;
                    unsigned int f = 0;
                    if (idx >= 0) f = ld_acq_u32(&g_flag[chain * NT + idx]);
                    const bool ready = (idx >= 0) && (f >= fbase);
                    const bool incl  = ready && (f == fbase + 1u);
                    const unsigned int br = __ballot_sync(0xffffffffu, ready);
                    const unsigned int bi = __ballot_sync(0xffffffffu, incl);
                    const unsigned int nr = ~br;
                    const int r = nr ? (__ffs(nr) - 1) : 32;   // consecutive ready
                    const unsigned int mask = (r >= 32) ? 0xffffffffu
                                                        : ((1u << r) - 1u);
                    const unsigned int ir = bi & mask;
                    if (ir) { m = base - (__ffs(ir) - 1); break; }
                    base -= r;                                 // consume aggregates
                    if (r == 0) __nanosleep(32);
                }
                if (tid == 0) s_m = m;
            }
            __syncthreads();
            const int m = s_m;

            // Phase V: independent value loads, one memory round.
            const size_t cvb = (size_t)(chain * NT) * SEGW + lane;
            excl = ld_rel_f32(&g_vinc[cvb + (size_t)m * SEGW]);
#pragma unroll 8
            for (int k = m + 1; k < ltile; ++k)
                excl += ld_rel_f32(&g_vagg[cvb + (size_t)k * SEGW]);

            // Publish inclusive.
            g_vinc[vidx] = excl + total;
            __threadfence();
            __syncthreads();
            if (tid == 0) st_rel_u32(&g_flag[fidx], fbase + 1u);
        }

        // ---- store outputs (coalesced) ----
        {
            float* q = Y + tile_row0(tloc) + lane;
#pragma unroll
            for (int i = 0; i < CHUNK; ++i) q[(size_t)i * INNER] = v[i] + excl;
        }

        if (tloc1 >= NTILES) break;
        tloc = tloc1;
    }
}

extern "C" void kernel_launch(void* const* d_in, const int* in_sizes, int n_in,
                              void* d_out, int out_size) {
    const float* X = (const float*)d_in[0];
    float*       Y = (float*)d_out;
    (void)in_sizes; (void)n_in; (void)out_size;

    scan_kernel<<<GRID, SEGW>>>(X, Y);
}

// round 10
// speedup vs baseline: 1.3997x; 1.3997x over previous
#include <cuda_runtime.h>
#include <stdint.h>

// X (B=4, L=8192, D=32, N=32) fp32, cumsum along L (axis=1).
// Inner = D*N = 1024 contiguous floats per (b,l).
#define BB      4
#define LL      8192
#define INNER   1024
#define SEGW    256                    // lanes per CTA (segment width)
#define NSEG    (INNER / SEGW)         // 4 segments
#define CHUNK   32                     // L rows per tile
#define NT      (LL / CHUNK)           // 256 L-tiles per chain
#define NCHAIN  (BB * NSEG)            // 16 independent (b,seg) chains
#define NTILES  (NCHAIN * NT)          // 4096 tiles per launch
#define GRID    592                    // persistent CTAs (4/SM x 148 SMs)
#define TPL     (NTILES + GRID)        // tickets consumed per launch (exact)
#define LOOKW   6                      // lookback window (independent loads)

// Decoupled-lookback state: packed {flag:32 | value_bits:32} per (tile, lane).
// Flag+value travel in ONE 8-byte relaxed access => no fences needed anywhere.
//   flag <  fbase   : stale (earlier launch)
//   flag == fbase   : aggregate available
//   flag == fbase+1 : inclusive prefix available
// fbase = 2*(ticket/TPL) + 2; g_ticket is monotonic forever (no init kernel).
__device__ unsigned long long g_state[(size_t)NTILES * SEGW];   // 8 MiB
__device__ unsigned int g_ticket = 0;

__device__ __forceinline__ unsigned long long ld_relaxed_u64(const unsigned long long* p) {
    unsigned long long v;
    asm volatile("ld.relaxed.gpu.global.b64 %0, [%1];" : "=l"(v) : "l"(p));
    return v;
}
__device__ __forceinline__ void st_relaxed_u64(unsigned long long* p, unsigned long long v) {
    asm volatile("st.relaxed.gpu.global.b64 [%0], %1;" :: "l"(p), "l"(v));
}
__device__ __forceinline__ unsigned long long pack_fv(unsigned int flag, float val) {
    return ((unsigned long long)flag << 32) | (unsigned long long)__float_as_uint(val);
}
__device__ __forceinline__ void cp_async16(uint32_t smem_addr, const void* gmem) {
    asm volatile("cp.async.cg.shared.global [%0], [%1], 16;"
                 :: "r"(smem_addr), "l"(gmem));
}
__device__ __forceinline__ void cp_async_commit() {
    asm volatile("cp.async.commit_group;");
}
__device__ __forceinline__ void cp_async_wait0() {
    asm volatile("cp.async.wait_group 0;");
}

// Element index of row 0, lane 0 of a tile.
__device__ __forceinline__ size_t tile_row0(int tloc) {
    const int chain = tloc & (NCHAIN - 1);
    const int ltile = tloc >> 4;               // NCHAIN = 16
    const int b     = chain >> 2;              // NSEG = 4
    const int seg   = chain & 3;
    return ((size_t)b * LL + (size_t)ltile * CHUNK) * INNER + (size_t)seg * SEGW;
}

__global__ __launch_bounds__(SEGW, 4)
void scan_kernel(const float* __restrict__ X, float* __restrict__ Y) {
    __shared__ float s_buf[CHUNK * SEGW];      // 32 KB staging
    __shared__ unsigned int s_t;

    const int tid  = (int)threadIdx.x;
    const int lane = tid;

    uint32_t s_base;
    asm("{ .reg .u64 t; cvta.to.shared.u64 t, %1; cvt.u32.u64 %0, t; }"
        : "=r"(s_base) : "l"(s_buf));

    if (tid == 0) s_t = atomicAdd(&g_ticket, 1u);
    __syncthreads();

    const unsigned int t0    = s_t;
    const unsigned int epoch = t0 / TPL;                 // launch-unique
    const unsigned int lb    = epoch * TPL;              // launch ticket base
    const unsigned int fbase = epoch * 2u + 2u;          // agg flag; incl = +1
    int tloc = (int)(t0 - lb);
    if (tloc >= NTILES) return;                          // terminating ticket

    // cp.async sweep geometry: 8 sweeps of 4 KB; thread covers 16 B per sweep.
    const int sub  = tid >> 6;                 // row-within-4 group
    const int colb = (tid & 63) * 16;          // byte column within row
    const uint32_t s_dst0 = s_base + (uint32_t)(sub * 1024 + colb);

    // Prologue: prefetch first tile.
    {
        const char* src = (const char*)(X + tile_row0(tloc));
#pragma unroll
        for (int s = 0; s < CHUNK / 4; ++s)
            cp_async16(s_dst0 + (uint32_t)s * 4096u,
                       src + (size_t)(s * 4 + sub) * (INNER * 4) + colb);
        cp_async_commit();
    }

    for (;;) {
        cp_async_wait0();
        __syncthreads();                       // staged tile visible to all

        // ---- load from smem + local inclusive scan ----
        float v[CHUNK];
#pragma unroll
        for (int i = 0; i < CHUNK; ++i) v[i] = s_buf[i * SEGW + lane];
#pragma unroll
        for (int i = 1; i < CHUNK; ++i) v[i] += v[i - 1];
        const float total = v[CHUNK - 1];

        const int chain = tloc & (NCHAIN - 1);
        const int ltile = tloc >> 4;
        const size_t chain_base = ((size_t)chain * NT) * SEGW + lane;
        unsigned long long* my_state = &g_state[chain_base + (size_t)ltile * SEGW];

        // Publish aggregate (inclusive for ltile 0) immediately — no fence:
        // flag and value are one 8-byte word.
        st_relaxed_u64(my_state,
                       pack_fv(ltile == 0 ? fbase + 1u : fbase, total));

        // Next ticket. (Write-after-read on s_t safe: last read before the
        // barrier above, in the previous iteration.)
        if (tid == 0) s_t = atomicAdd(&g_ticket, 1u);
        __syncthreads();                       // LDS drained + s_t visible
        const int tloc1 = (int)(s_t - lb);

        // Prefetch next tile into the reusable buffer; overlaps lookback.
        if (tloc1 < NTILES) {
            const char* src = (const char*)(X + tile_row0(tloc1));
#pragma unroll
            for (int s = 0; s < CHUNK / 4; ++s)
                cp_async16(s_dst0 + (uint32_t)s * 4096u,
                           src + (size_t)(s * 4 + sub) * (INNER * 4) + colb);
            cp_async_commit();
        }

        // ---- decoupled lookback (LOOKW independent loads per round) ----
        float excl = 0.0f;
        if (ltile != 0) {
            const unsigned long long* st_row = &g_state[chain_base];
            int pt = ltile - 1;
            for (;;) {
                unsigned long long w[LOOKW];
                const int n = (pt + 1 < LOOKW) ? (pt + 1) : LOOKW;
#pragma unroll
                for (int j = 0; j < LOOKW; ++j)
                    if (j < n) w[j] = ld_relaxed_u64(st_row + (size_t)(pt - j) * SEGW);

                int consumed = 0;
                bool done = false;
#pragma unroll
                for (int j = 0; j < LOOKW; ++j) {
                    if (j >= n || done) continue;
                    unsigned int f = (unsigned int)(w[j] >> 32);
                    if (f < fbase) break;                      // stale: stop
                    excl += __uint_as_float((unsigned int)w[j]);
                    ++consumed;
                    if (f == fbase + 1u) done = true;          // found inclusive
                }
                pt -= consumed;
                if (done) break;
                if (consumed == 0) __nanosleep(32);
            }
            st_relaxed_u64(my_state, pack_fv(fbase + 1u, excl + total));
        }

        // ---- store outputs (coalesced) ----
        {
            float* q = Y + tile_row0(tloc) + lane;
#pragma unroll
            for (int i = 0; i < CHUNK; ++i) q[(size_t)i * INNER] = v[i] + excl;
        }

        if (tloc1 >= NTILES) break;
        tloc = tloc1;
    }
}

extern "C" void kernel_launch(void* const* d_in, const int* in_sizes, int n_in,
                              void* d_out, int out_size) {
    const float* X = (const float*)d_in[0];
    float*       Y = (float*)d_out;
    (void)in_sizes; (void)n_in; (void)out_size;

    scan_kernel<<<GRID, SEGW>>>(X, Y);
}